// round 1
// baseline (speedup 1.0000x reference)
#include <cuda_runtime.h>
#include <cuda_bf16.h>
#include <cstdint>

// Problem constants (shapes are fixed by the dataset)
#define IN_DIM  256
#define OUT_DIM 128
#define MAX_NODES 100000

// Scratch for h = X @ W   (100000 x 128 fp32 = 51.2 MB; fits in L2 for the gather phase)
__device__ float g_h[(size_t)MAX_NODES * OUT_DIM];

// ---------------------------------------------------------------------------
// Kernel 1: init out[n][j] = b[j]  (folds bias epilogue into the zero-init)
// ---------------------------------------------------------------------------
__global__ void init_out_kernel(float* __restrict__ out, const float* __restrict__ b, int n_vec4) {
    int i = blockIdx.x * blockDim.x + threadIdx.x;
    if (i < n_vec4) {
        // out row is 128 floats = 32 float4; bias repeats every 32 float4
        float4 bv = reinterpret_cast<const float4*>(b)[i & 31];
        reinterpret_cast<float4*>(out)[i] = bv;
    }
}

// ---------------------------------------------------------------------------
// Kernel 2: tiled SGEMM  h[M,128] = X[M,256] @ W[256,128]
// BM=128 BN=128 BK=32, 256 threads, TM=TN=8
// ---------------------------------------------------------------------------
#define BM 128
#define BN 128
#define BK 32
#define TM 8
#define TN 8

__global__ __launch_bounds__(256, 2)
void gemm_kernel(const float* __restrict__ A, const float* __restrict__ B,
                 float* __restrict__ C, int M) {
    __shared__ float As[BK][BM];   // transposed A tile
    __shared__ float Bs[BK][BN];

    const int tid = threadIdx.x;
    const int rowBase = blockIdx.x * BM;
    const int tr = tid >> 4;       // 0..15
    const int tc = tid & 15;       // 0..15

    float acc[TM][TN];
#pragma unroll
    for (int i = 0; i < TM; i++)
#pragma unroll
        for (int j = 0; j < TN; j++) acc[i][j] = 0.0f;

    for (int k0 = 0; k0 < IN_DIM; k0 += BK) {
        // Cooperative loads: 4 float4 of A-tile and 4 float4 of B-tile per thread
#pragma unroll
        for (int i = 0; i < 4; i++) {
            int s = tid + i * 256;
            // A tile: 128 rows x 32 cols = 1024 float4 (8 float4 per row)
            int arow = s >> 3;
            int akq  = s & 7;
            float4 v = make_float4(0.f, 0.f, 0.f, 0.f);
            int gr = rowBase + arow;
            if (gr < M)
                v = *reinterpret_cast<const float4*>(A + (size_t)gr * IN_DIM + k0 + akq * 4);
            As[akq * 4 + 0][arow] = v.x;
            As[akq * 4 + 1][arow] = v.y;
            As[akq * 4 + 2][arow] = v.z;
            As[akq * 4 + 3][arow] = v.w;
            // B tile: 32 rows x 128 cols = 1024 float4 (32 float4 per row)
            int brow = s >> 5;
            int bq   = s & 31;
            float4 w = *reinterpret_cast<const float4*>(B + (size_t)(k0 + brow) * OUT_DIM + bq * 4);
            *reinterpret_cast<float4*>(&Bs[brow][bq * 4]) = w;
        }
        __syncthreads();

#pragma unroll
        for (int kk = 0; kk < BK; kk++) {
            float a[TM], bb[TN];
#pragma unroll
            for (int i = 0; i < TM; i++) a[i] = As[kk][tr * TM + i];
#pragma unroll
            for (int j = 0; j < TN; j++) bb[j] = Bs[kk][tc * TN + j];
#pragma unroll
            for (int i = 0; i < TM; i++)
#pragma unroll
                for (int j = 0; j < TN; j++) acc[i][j] += a[i] * bb[j];
        }
        __syncthreads();
    }

    // store TMxTN micro-tile as float4 pairs
#pragma unroll
    for (int i = 0; i < TM; i++) {
        int gr = rowBase + tr * TM + i;
        if (gr < M) {
            float4* cp = reinterpret_cast<float4*>(C + (size_t)gr * OUT_DIM + tc * TN);
            cp[0] = make_float4(acc[i][0], acc[i][1], acc[i][2], acc[i][3]);
            cp[1] = make_float4(acc[i][4], acc[i][5], acc[i][6], acc[i][7]);
        }
    }
}

// ---------------------------------------------------------------------------
// Kernel 3: edge scatter.  One warp per edge per iteration:
//   lane l handles float4 chunk l of the 128-wide row.
//   out[dst*128 + 4l .. +3] += val * h[src*128 + 4l .. +3]  via red.global.add.v4.f32
// ---------------------------------------------------------------------------
__global__ __launch_bounds__(256)
void scatter_kernel(const int* __restrict__ src, const int* __restrict__ dst,
                    const float* __restrict__ val, float* __restrict__ out, int E) {
    const int lane = threadIdx.x & 31;
    const int warpsPerGrid = (gridDim.x * blockDim.x) >> 5;
    int w = (blockIdx.x * blockDim.x + threadIdx.x) >> 5;

    for (int e = w; e < E; e += warpsPerGrid) {
        int s = __ldg(src + e);
        int d = __ldg(dst + e);
        float v = __ldg(val + e);

        float4 m = reinterpret_cast<const float4*>(g_h + (size_t)s * OUT_DIM)[lane];
        m.x *= v; m.y *= v; m.z *= v; m.w *= v;

        float* o = out + (size_t)d * OUT_DIM + lane * 4;
        asm volatile("red.global.add.v4.f32 [%0], {%1, %2, %3, %4};"
                     :: "l"(o), "f"(m.x), "f"(m.y), "f"(m.z), "f"(m.w)
                     : "memory");
    }
}

// ---------------------------------------------------------------------------
// Launch
// Inputs (metadata order): 0 feature_map [N,256] f32, 1 edge_src [E] i32,
// 2 edge_dst [E] i32, 3 edge_vals [E] f32, 4 weights [256,128] f32, 5 b [128] f32
// Output: [N,128] f32
// ---------------------------------------------------------------------------
extern "C" void kernel_launch(void* const* d_in, const int* in_sizes, int n_in,
                              void* d_out, int out_size) {
    const float* X   = (const float*)d_in[0];
    const int*   src = (const int*)  d_in[1];
    const int*   dst = (const int*)  d_in[2];
    const float* ev  = (const float*)d_in[3];
    const float* W   = (const float*)d_in[4];
    const float* b   = (const float*)d_in[5];
    float* out = (float*)d_out;

    const int E = in_sizes[1];
    const int M = out_size / OUT_DIM;   // number of nodes

    // 1) out = broadcast(b)
    {
        int n_vec4 = out_size / 4;
        init_out_kernel<<<(n_vec4 + 255) / 256, 256>>>(out, b, n_vec4);
    }

    // 2) h = X @ W
    {
        float* h;
        cudaGetSymbolAddress((void**)&h, g_h);
        int grid = (M + BM - 1) / BM;
        gemm_kernel<<<grid, 256>>>(X, W, h, M);
    }

    // 3) out[dst] += val * h[src]
    {
        int grid = 148 * 16;   // persistent-ish: each warp loops over strided edges
        scatter_kernel<<<grid, 256>>>(src, dst, ev, out, E);
    }
}